// round 3
// baseline (speedup 1.0000x reference)
#include <cuda_runtime.h>
#include <cuda_bf16.h>
#include <math.h>

// Problem constants
#define B_SZ   64
#define T_ENC  1024
#define D_ENC  512
#define Q_DIM  1024
#define H_DIM  256
#define M_MIX  5
#define EPS    1e-5f

#define TSPLIT 16
#define T_CHUNK (T_ENC / TSPLIT)   // 64

// scratch for partial context sums: 64 * 16 * 512 floats = 2 MB
__device__ float g_ctx_partial[B_SZ * TSPLIT * D_ENC];

__device__ __forceinline__ float stable_sigmoid(float z) {
    if (z >= 0.0f) {
        return 1.0f / (1.0f + expf(-z));
    } else {
        float e = expf(z);
        return e / (1.0f + e);
    }
}

__device__ __forceinline__ float softplus(float x) {
    // log(1+exp(x)) = max(x,0) + log1p(exp(-|x|))
    return fmaxf(x, 0.0f) + log1pf(expf(-fabsf(x)));
}

// ---------------------------------------------------------------------------
// Kernel A: per-batch fused MLP -> mixture params -> alpha
// grid = 64 blocks (one per batch), 256 threads
// ---------------------------------------------------------------------------
__global__ __launch_bounds__(256) void mol_alpha_kernel(
    const float* __restrict__ att,      // [B, Q_DIM]
    const unsigned char* __restrict__ mask, // [B, T_ENC] (bool)
    const float* __restrict__ mu_prev,  // [B, M]
    const float* __restrict__ W1,       // [Q_DIM, 256]
    const float* __restrict__ b1,       // [256]
    const float* __restrict__ W2,       // [256, 15]
    const float* __restrict__ b2,       // [15]
    float* __restrict__ alpha_out)      // [B, T_ENC]
{
    const int b   = blockIdx.x;
    const int tid = threadIdx.x;

    __shared__ float att_s[Q_DIM];
    __shared__ float h_s[H_DIM];
    __shared__ float params_s[3 * M_MIX];
    __shared__ float w_s[M_MIX], mu_s[M_MIX], isig_s[M_MIX];

    // load att row into shared
    for (int k = tid; k < Q_DIM; k += 256)
        att_s[k] = att[(size_t)b * Q_DIM + k];
    __syncthreads();

    // h = relu(att @ W1 + b1)  — thread tid owns output column tid
    {
        float acc = b1[tid];
        #pragma unroll 8
        for (int k = 0; k < Q_DIM; k++)
            acc = fmaf(att_s[k], W1[(size_t)k * H_DIM + tid], acc);
        h_s[tid] = fmaxf(acc, 0.0f);
    }
    __syncthreads();

    // params = h @ W2 + b2 — 15 outputs, threads 0..14
    if (tid < 3 * M_MIX) {
        float p = b2[tid];
        #pragma unroll 8
        for (int k = 0; k < H_DIM; k++)
            p = fmaf(h_s[k], W2[k * (3 * M_MIX) + tid], p);
        params_s[tid] = p;
    }
    __syncthreads();

    // mixture params — threads 0..4, each redundantly computes softmax denom
    if (tid < M_MIX) {
        float mx = params_s[0];
        #pragma unroll
        for (int m = 1; m < M_MIX; m++) mx = fmaxf(mx, params_s[m]);
        float den = 0.0f;
        #pragma unroll
        for (int m = 0; m < M_MIX; m++) den += expf(params_s[m] - mx);
        float w = expf(params_s[tid] - mx) / den + EPS;

        float sigma = softplus(params_s[M_MIX + tid]) + EPS;
        float Delta = softplus(params_s[2 * M_MIX + tid]);
        float mu    = mu_prev[b * M_MIX + tid] + Delta;

        w_s[tid]    = w;
        mu_s[tid]   = mu;
        isig_s[tid] = 1.0f / sigma;
    }
    __syncthreads();

    // alpha[t] = F(t+1.5) - F(t+0.5), F(j) = sum_m w_m / (1 + sigmoid((mu_m - j)/sigma_m))
    for (int t = tid; t < T_ENC; t += 256) {
        float j0 = (float)t + 0.5f;
        float j1 = (float)t + 1.5f;
        float F0 = 0.0f, F1 = 0.0f;
        #pragma unroll
        for (int m = 0; m < M_MIX; m++) {
            float mu = mu_s[m], is = isig_s[m], w = w_s[m];
            float s0 = stable_sigmoid((mu - j0) * is);
            float s1 = stable_sigmoid((mu - j1) * is);
            F0 += w / (1.0f + s0);
            F1 += w / (1.0f + s1);
        }
        float a = F1 - F0;
        if (a == 0.0f) a = EPS;
        if (mask[(size_t)b * T_ENC + t]) a = 0.0f;
        alpha_out[(size_t)b * T_ENC + t] = a;
    }
}

// ---------------------------------------------------------------------------
// Kernel B: partial context sums. grid (B, TSPLIT), 128 threads.
// Each thread owns a float4 of the d-dimension; streams T_CHUNK rows.
// ---------------------------------------------------------------------------
__global__ __launch_bounds__(128) void ctx_partial_kernel(
    const float* __restrict__ memory,   // [B, T, D]
    const float* __restrict__ alpha)    // [B, T]
{
    const int b   = blockIdx.x;
    const int ts  = blockIdx.y;
    const int tid = threadIdx.x;      // 128 threads * float4 = 512 dims

    __shared__ float a_s[T_CHUNK];
    if (tid < T_CHUNK)
        a_s[tid] = alpha[(size_t)b * T_ENC + ts * T_CHUNK + tid];
    __syncthreads();

    const float4* mem4 = reinterpret_cast<const float4*>(
        memory + ((size_t)b * T_ENC + (size_t)ts * T_CHUNK) * D_ENC);

    float4 acc = make_float4(0.f, 0.f, 0.f, 0.f);
    #pragma unroll 4
    for (int t = 0; t < T_CHUNK; t++) {
        float a = a_s[t];
        float4 v = mem4[(size_t)t * 128 + tid];
        acc.x = fmaf(a, v.x, acc.x);
        acc.y = fmaf(a, v.y, acc.y);
        acc.z = fmaf(a, v.z, acc.z);
        acc.w = fmaf(a, v.w, acc.w);
    }

    float4* out = reinterpret_cast<float4*>(
        g_ctx_partial + ((size_t)(b * TSPLIT + ts)) * D_ENC);
    out[tid] = acc;
}

// ---------------------------------------------------------------------------
// Kernel C: deterministic reduction of TSPLIT partials -> context
// ---------------------------------------------------------------------------
__global__ __launch_bounds__(256) void ctx_reduce_kernel(float* __restrict__ ctx)
{
    int i = blockIdx.x * blockDim.x + threadIdx.x;  // 0 .. B*D-1
    if (i >= B_SZ * D_ENC) return;
    int b = i >> 9;        // /512
    int d = i & (D_ENC - 1);
    float s = 0.0f;
    #pragma unroll
    for (int p = 0; p < TSPLIT; p++)
        s += g_ctx_partial[((size_t)(b * TSPLIT + p)) * D_ENC + d];
    ctx[i] = s;
}

// ---------------------------------------------------------------------------
// kernel_launch: inputs in setup_inputs order:
//   0 att_rnn_h [64*1024], 1 memory [64*1024*512], 2 mask [64*1024] (bool),
//   3 mu_prev [64*5], 4 W1 [1024*256], 5 b1 [256], 6 W2 [256*15], 7 b2 [15]
// output: context [64*512] then alpha [64*1024]
// ---------------------------------------------------------------------------
extern "C" void kernel_launch(void* const* d_in, const int* in_sizes, int n_in,
                              void* d_out, int out_size) {
    const float*         att     = (const float*)d_in[0];
    const float*         memory  = (const float*)d_in[1];
    const unsigned char* mask    = (const unsigned char*)d_in[2];
    const float*         mu_prev = (const float*)d_in[3];
    const float*         W1      = (const float*)d_in[4];
    const float*         b1      = (const float*)d_in[5];
    const float*         W2      = (const float*)d_in[6];
    const float*         b2      = (const float*)d_in[7];

    float* ctx_out   = (float*)d_out;                   // [64*512]
    float* alpha_out = (float*)d_out + B_SZ * D_ENC;    // [64*1024]

    mol_alpha_kernel<<<B_SZ, 256>>>(att, mask, mu_prev, W1, b1, W2, b2, alpha_out);

    dim3 gridB(B_SZ, TSPLIT);
    ctx_partial_kernel<<<gridB, 128>>>(memory, alpha_out);

    ctx_reduce_kernel<<<(B_SZ * D_ENC + 255) / 256, 256>>>(ctx_out);
}

// round 7
// speedup vs baseline: 1.5083x; 1.5083x over previous
#include <cuda_runtime.h>
#include <cuda_bf16.h>
#include <math.h>

// Problem constants
#define B_SZ   64
#define T_ENC  1024
#define D_ENC  512
#define Q_DIM  1024
#define H_DIM  256
#define M_MIX  5
#define EPS    1e-5f

#define TSPLIT 16
#define T_CHUNK (T_ENC / TSPLIT)   // 64

// scratch (device globals, no allocation)
__device__ float g_ctx_partial[B_SZ * TSPLIT * D_ENC];  // 2 MB
__device__ float g_h[B_SZ * H_DIM];                     // hidden layer
__device__ float g_params[B_SZ * 16];                   // w[5], mu[5], isig[5] per batch

__device__ __forceinline__ float stable_sigmoid(float z) {
    if (z >= 0.0f) {
        return 1.0f / (1.0f + expf(-z));
    } else {
        float e = expf(z);
        return e / (1.0f + e);
    }
}

__device__ __forceinline__ float softplus(float x) {
    return fmaxf(x, 0.0f) + log1pf(expf(-fabsf(x)));
}

// ---------------------------------------------------------------------------
// K1: h = relu(att @ W1 + b1)
// grid (16 batch-groups, 8 col-chunks), 256 threads = 32 cols x 8 k-groups.
// Each block: 4 batches (independent accumulators), k-split 8x across warps.
// ---------------------------------------------------------------------------
__global__ __launch_bounds__(256) void mlp1_kernel(
    const float* __restrict__ att,   // [B, Q_DIM]
    const float* __restrict__ W1,    // [Q_DIM, H_DIM]
    const float* __restrict__ b1)    // [H_DIM]
{
    const int bg = blockIdx.x;            // batch group: batches bg*4 .. bg*4+3
    const int cc = blockIdx.y;            // col chunk:  cols cc*32 .. cc*32+31
    const int c  = threadIdx.x & 31;
    const int g  = threadIdx.x >> 5;      // k-group 0..7
    const int col = cc * 32 + c;

    __shared__ float att_s[4][Q_DIM];     // 16 KB
    __shared__ float red[4][8][32];       // 4 KB

    // load 4 att rows (vectorized)
    {
        const float4* src = reinterpret_cast<const float4*>(att + (size_t)bg * 4 * Q_DIM);
        float4* dst = reinterpret_cast<float4*>(&att_s[0][0]);
        #pragma unroll
        for (int i = threadIdx.x; i < 4 * Q_DIM / 4; i += 256)
            dst[i] = src[i];
    }
    __syncthreads();

    float acc0 = 0.f, acc1 = 0.f, acc2 = 0.f, acc3 = 0.f;
    const int kbase = g * 128;
    const float* w1p = W1 + (size_t)kbase * H_DIM + col;
    #pragma unroll 4
    for (int kk = 0; kk < 128; kk++) {
        float w = w1p[(size_t)kk * H_DIM];
        int k = kbase + kk;
        acc0 = fmaf(att_s[0][k], w, acc0);
        acc1 = fmaf(att_s[1][k], w, acc1);
        acc2 = fmaf(att_s[2][k], w, acc2);
        acc3 = fmaf(att_s[3][k], w, acc3);
    }
    red[0][g][c] = acc0;
    red[1][g][c] = acc1;
    red[2][g][c] = acc2;
    red[3][g][c] = acc3;
    __syncthreads();

    if (threadIdx.x < 128) {
        int i  = threadIdx.x >> 5;   // batch within group
        int c2 = threadIdx.x & 31;
        float s = b1[cc * 32 + c2];
        #pragma unroll
        for (int gg = 0; gg < 8; gg++) s += red[i][gg][c2];
        g_h[(size_t)(bg * 4 + i) * H_DIM + cc * 32 + c2] = fmaxf(s, 0.0f);
    }
}

// ---------------------------------------------------------------------------
// K2: params = h @ W2 + b2 -> mixture transforms -> g_params
// grid 64 blocks, 32 threads (one warp per batch)
// ---------------------------------------------------------------------------
__global__ __launch_bounds__(32) void mlp2_kernel(
    const float* __restrict__ W2,       // [H_DIM, 15]
    const float* __restrict__ b2,       // [15]
    const float* __restrict__ mu_prev)  // [B, M]
{
    const int b   = blockIdx.x;
    const int tid = threadIdx.x;

    __shared__ float h_s[H_DIM];
    __shared__ float p_s[16];

    {
        const float4* src = reinterpret_cast<const float4*>(g_h + (size_t)b * H_DIM);
        float4* dst = reinterpret_cast<float4*>(h_s);
        #pragma unroll
        for (int i = tid; i < H_DIM / 4; i += 32)
            dst[i] = src[i];
    }
    __syncwarp();

    if (tid < 3 * M_MIX) {
        float p = b2[tid];
        #pragma unroll 8
        for (int k = 0; k < H_DIM; k++)
            p = fmaf(h_s[k], W2[k * (3 * M_MIX) + tid], p);
        p_s[tid] = p;
    }
    __syncwarp();

    if (tid < M_MIX) {
        float mx = p_s[0];
        #pragma unroll
        for (int m = 1; m < M_MIX; m++) mx = fmaxf(mx, p_s[m]);
        float den = 0.0f;
        #pragma unroll
        for (int m = 0; m < M_MIX; m++) den += expf(p_s[m] - mx);
        float w = expf(p_s[tid] - mx) / den + EPS;

        float sigma = softplus(p_s[M_MIX + tid]) + EPS;
        float Delta = softplus(p_s[2 * M_MIX + tid]);
        float mu    = mu_prev[b * M_MIX + tid] + Delta;

        g_params[b * 16 + tid]      = w;
        g_params[b * 16 + 5 + tid]  = mu;
        g_params[b * 16 + 10 + tid] = 1.0f / sigma;
    }
}

// ---------------------------------------------------------------------------
// K3: fused alpha + partial context. grid (B, TSPLIT), 128 threads.
// Threads 0..63 compute the block's 64 alphas; then all stream the tile.
// ---------------------------------------------------------------------------
__global__ __launch_bounds__(128) void alpha_ctx_kernel(
    const float* __restrict__ memory,        // [B, T, D]
    const unsigned char* __restrict__ mask,  // [B, T]
    float* __restrict__ alpha_out)           // [B, T]
{
    const int b   = blockIdx.x;
    const int ts  = blockIdx.y;
    const int tid = threadIdx.x;

    __shared__ float a_s[T_CHUNK];
    __shared__ float par_s[16];

    if (tid < 15) par_s[tid] = g_params[b * 16 + tid];
    __syncthreads();

    if (tid < T_CHUNK) {
        int t = ts * T_CHUNK + tid;
        float j0 = (float)t + 0.5f;
        float j1 = (float)t + 1.5f;
        float F0 = 0.0f, F1 = 0.0f;
        #pragma unroll
        for (int m = 0; m < M_MIX; m++) {
            float w  = par_s[m];
            float mu = par_s[5 + m];
            float is = par_s[10 + m];
            float s0 = stable_sigmoid((mu - j0) * is);
            float s1 = stable_sigmoid((mu - j1) * is);
            F0 += w / (1.0f + s0);
            F1 += w / (1.0f + s1);
        }
        float a = F1 - F0;
        if (a == 0.0f) a = EPS;
        if (mask[(size_t)b * T_ENC + t]) a = 0.0f;
        alpha_out[(size_t)b * T_ENC + t] = a;
        a_s[tid] = a;
    }
    __syncthreads();

    const float4* mem4 = reinterpret_cast<const float4*>(
        memory + ((size_t)b * T_ENC + (size_t)ts * T_CHUNK) * D_ENC);

    float4 acc = make_float4(0.f, 0.f, 0.f, 0.f);
    #pragma unroll 4
    for (int t = 0; t < T_CHUNK; t++) {
        float a = a_s[t];
        float4 v = mem4[(size_t)t * 128 + tid];
        acc.x = fmaf(a, v.x, acc.x);
        acc.y = fmaf(a, v.y, acc.y);
        acc.z = fmaf(a, v.z, acc.z);
        acc.w = fmaf(a, v.w, acc.w);
    }

    float4* out = reinterpret_cast<float4*>(
        g_ctx_partial + ((size_t)(b * TSPLIT + ts)) * D_ENC);
    out[tid] = acc;
}

// ---------------------------------------------------------------------------
// K4: deterministic reduction of TSPLIT partials -> context
// ---------------------------------------------------------------------------
__global__ __launch_bounds__(256) void ctx_reduce_kernel(float* __restrict__ ctx)
{
    int i = blockIdx.x * blockDim.x + threadIdx.x;
    if (i >= B_SZ * D_ENC) return;
    int b = i >> 9;
    int d = i & (D_ENC - 1);
    float s = 0.0f;
    #pragma unroll
    for (int p = 0; p < TSPLIT; p++)
        s += g_ctx_partial[((size_t)(b * TSPLIT + p)) * D_ENC + d];
    ctx[i] = s;
}

// ---------------------------------------------------------------------------
// kernel_launch
// inputs: 0 att_rnn_h, 1 memory, 2 mask(bool), 3 mu_prev, 4 W1, 5 b1, 6 W2, 7 b2
// output: context [64*512] then alpha [64*1024]
// ---------------------------------------------------------------------------
extern "C" void kernel_launch(void* const* d_in, const int* in_sizes, int n_in,
                              void* d_out, int out_size) {
    const float*         att     = (const float*)d_in[0];
    const float*         memory  = (const float*)d_in[1];
    const unsigned char* mask    = (const unsigned char*)d_in[2];
    const float*         mu_prev = (const float*)d_in[3];
    const float*         W1      = (const float*)d_in[4];
    const float*         b1      = (const float*)d_in[5];
    const float*         W2      = (const float*)d_in[6];
    const float*         b2      = (const float*)d_in[7];

    float* ctx_out   = (float*)d_out;
    float* alpha_out = (float*)d_out + B_SZ * D_ENC;

    dim3 grid1(B_SZ / 4, H_DIM / 32);   // (16, 8)
    mlp1_kernel<<<grid1, 256>>>(att, W1, b1);

    mlp2_kernel<<<B_SZ, 32>>>(W2, b2, mu_prev);

    dim3 grid3(B_SZ, TSPLIT);
    alpha_ctx_kernel<<<grid3, 128>>>(memory, mask, alpha_out);

    ctx_reduce_kernel<<<(B_SZ * D_ENC + 255) / 256, 256>>>(ctx_out);
}

// round 8
// speedup vs baseline: 2.7382x; 1.8154x over previous
#include <cuda_runtime.h>
#include <cuda_bf16.h>
#include <math.h>

// Problem constants
#define B_SZ   64
#define T_ENC  1024
#define D_ENC  512
#define Q_DIM  1024
#define H_DIM  256
#define M_MIX  5
#define EPS    1e-5f

#define TSPLIT 16
#define T_CHUNK (T_ENC / TSPLIT)   // 64

// scratch (device globals, no allocation)
__device__ float g_ctx_partial[B_SZ * TSPLIT * D_ENC];  // 2 MB

__device__ __forceinline__ float stable_sigmoid(float z) {
    if (z >= 0.0f) {
        return 1.0f / (1.0f + expf(-z));
    } else {
        float e = expf(z);
        return e / (1.0f + e);
    }
}

__device__ __forceinline__ float softplus(float x) {
    return fmaxf(x, 0.0f) + log1pf(expf(-fabsf(x)));
}

// ---------------------------------------------------------------------------
// K_A: fully fused per-batch parameter path + alpha.
// grid = 64 (one block per batch), 1024 threads.
//   phase 1: h = relu(att @ W1 + b1)   (256 cols x 4 k-groups, chain=256)
//   phase 2: params = h @ W2 + b2      (15 warps, warp-shuffle dot products)
//   phase 3: mixture transforms        (5 threads)
//   phase 4: alpha[t] for t=tid        (1024 threads)
// ---------------------------------------------------------------------------
__global__ __launch_bounds__(1024) void mol_params_alpha_kernel(
    const float* __restrict__ att,           // [B, Q_DIM]
    const unsigned char* __restrict__ mask,  // [B, T_ENC]
    const float* __restrict__ mu_prev,       // [B, M]
    const float* __restrict__ W1,            // [Q_DIM, H_DIM]
    const float* __restrict__ b1,            // [H_DIM]
    const float* __restrict__ W2,            // [H_DIM, 15]
    const float* __restrict__ b2,            // [15]
    float* __restrict__ alpha_out)           // [B, T_ENC]
{
    const int b    = blockIdx.x;
    const int tid  = threadIdx.x;
    const int lane = tid & 31;
    const int wid  = tid >> 5;               // 0..31

    __shared__ float att_s[Q_DIM];            // 4 KB
    __shared__ float red[4][H_DIM];           // 4 KB
    __shared__ float h_s[H_DIM];              // 1 KB
    __shared__ float p_s[16];
    __shared__ float par_s[16];

    // load att row (float4 x 256)
    if (tid < Q_DIM / 4) {
        reinterpret_cast<float4*>(att_s)[tid] =
            reinterpret_cast<const float4*>(att + (size_t)b * Q_DIM)[tid];
    }
    __syncthreads();

    // phase 1: MLP layer 1
    {
        const int col = tid & (H_DIM - 1);    // 0..255
        const int g   = tid >> 8;             // 0..3
        const int kbase = g * 256;
        const float* w1p = W1 + (size_t)kbase * H_DIM + col;
        float acc = 0.0f;
        #pragma unroll 8
        for (int kk = 0; kk < 256; kk++)
            acc = fmaf(att_s[kbase + kk], w1p[(size_t)kk * H_DIM], acc);
        red[g][col] = acc;
    }
    __syncthreads();
    if (tid < H_DIM) {
        float s = b1[tid] + red[0][tid] + red[1][tid] + red[2][tid] + red[3][tid];
        h_s[tid] = fmaxf(s, 0.0f);
    }
    __syncthreads();

    // phase 2: params = h @ W2 + b2 — warp wid handles output wid (wid < 15)
    if (wid < 3 * M_MIX) {
        float acc = 0.0f;
        #pragma unroll
        for (int i = 0; i < H_DIM / 32; i++) {
            int k = i * 32 + lane;
            acc = fmaf(h_s[k], W2[k * (3 * M_MIX) + wid], acc);
        }
        #pragma unroll
        for (int off = 16; off > 0; off >>= 1)
            acc += __shfl_down_sync(0xffffffffu, acc, off);
        if (lane == 0) p_s[wid] = acc + b2[wid];
    }
    __syncthreads();

    // phase 3: mixture transforms
    if (tid < M_MIX) {
        float mx = p_s[0];
        #pragma unroll
        for (int m = 1; m < M_MIX; m++) mx = fmaxf(mx, p_s[m]);
        float den = 0.0f;
        #pragma unroll
        for (int m = 0; m < M_MIX; m++) den += expf(p_s[m] - mx);
        float w = expf(p_s[tid] - mx) / den + EPS;

        float sigma = softplus(p_s[M_MIX + tid]) + EPS;
        float Delta = softplus(p_s[2 * M_MIX + tid]);
        float mu    = mu_prev[b * M_MIX + tid] + Delta;

        par_s[tid]      = w;
        par_s[5 + tid]  = mu;
        par_s[10 + tid] = 1.0f / sigma;
    }
    __syncthreads();

    // phase 4: alpha for t = tid
    {
        const int t = tid;
        float j0 = (float)t + 0.5f;
        float j1 = (float)t + 1.5f;
        float F0 = 0.0f, F1 = 0.0f;
        #pragma unroll
        for (int m = 0; m < M_MIX; m++) {
            float w  = par_s[m];
            float mu = par_s[5 + m];
            float is = par_s[10 + m];
            float s0 = stable_sigmoid((mu - j0) * is);
            float s1 = stable_sigmoid((mu - j1) * is);
            F0 += w / (1.0f + s0);
            F1 += w / (1.0f + s1);
        }
        float a = F1 - F0;
        if (a == 0.0f) a = EPS;
        if (mask[(size_t)b * T_ENC + t]) a = 0.0f;
        alpha_out[(size_t)b * T_ENC + t] = a;
    }
}

// ---------------------------------------------------------------------------
// K_B: pure streaming partial context. grid (B, TSPLIT), 128 threads.
// ---------------------------------------------------------------------------
__global__ __launch_bounds__(128) void ctx_partial_kernel(
    const float* __restrict__ memory,   // [B, T, D]
    const float* __restrict__ alpha)    // [B, T]
{
    const int b   = blockIdx.x;
    const int ts  = blockIdx.y;
    const int tid = threadIdx.x;

    __shared__ float a_s[T_CHUNK];
    if (tid < T_CHUNK)
        a_s[tid] = alpha[(size_t)b * T_ENC + ts * T_CHUNK + tid];
    __syncthreads();

    const float4* mem4 = reinterpret_cast<const float4*>(
        memory + ((size_t)b * T_ENC + (size_t)ts * T_CHUNK) * D_ENC);

    float4 acc = make_float4(0.f, 0.f, 0.f, 0.f);
    #pragma unroll 8
    for (int t = 0; t < T_CHUNK; t++) {
        float a = a_s[t];
        float4 v = __ldcs(&mem4[(size_t)t * 128 + tid]);   // streaming, no L2 reuse
        acc.x = fmaf(a, v.x, acc.x);
        acc.y = fmaf(a, v.y, acc.y);
        acc.z = fmaf(a, v.z, acc.z);
        acc.w = fmaf(a, v.w, acc.w);
    }

    float4* out = reinterpret_cast<float4*>(
        g_ctx_partial + ((size_t)(b * TSPLIT + ts)) * D_ENC);
    out[tid] = acc;
}

// ---------------------------------------------------------------------------
// K_C: deterministic reduction. grid 256 x 128 threads (1 elem/thread).
// ---------------------------------------------------------------------------
__global__ __launch_bounds__(128) void ctx_reduce_kernel(float* __restrict__ ctx)
{
    int i = blockIdx.x * 128 + threadIdx.x;   // 0 .. 32767
    int b = i >> 9;
    int d = i & (D_ENC - 1);
    const float* p0 = g_ctx_partial + (size_t)b * TSPLIT * D_ENC + d;
    float s = 0.0f;
    #pragma unroll
    for (int p = 0; p < TSPLIT; p++)
        s += p0[(size_t)p * D_ENC];
    ctx[i] = s;
}

// ---------------------------------------------------------------------------
// kernel_launch
// inputs: 0 att_rnn_h, 1 memory, 2 mask(bool), 3 mu_prev, 4 W1, 5 b1, 6 W2, 7 b2
// output: context [64*512] then alpha [64*1024]
// ---------------------------------------------------------------------------
extern "C" void kernel_launch(void* const* d_in, const int* in_sizes, int n_in,
                              void* d_out, int out_size) {
    const float*         att     = (const float*)d_in[0];
    const float*         memory  = (const float*)d_in[1];
    const unsigned char* mask    = (const unsigned char*)d_in[2];
    const float*         mu_prev = (const float*)d_in[3];
    const float*         W1      = (const float*)d_in[4];
    const float*         b1      = (const float*)d_in[5];
    const float*         W2      = (const float*)d_in[6];
    const float*         b2      = (const float*)d_in[7];

    float* ctx_out   = (float*)d_out;
    float* alpha_out = (float*)d_out + B_SZ * D_ENC;

    mol_params_alpha_kernel<<<B_SZ, 1024>>>(att, mask, mu_prev, W1, b1, W2, b2, alpha_out);

    dim3 gridB(B_SZ, TSPLIT);
    ctx_partial_kernel<<<gridB, 128>>>(memory, alpha_out);

    ctx_reduce_kernel<<<B_SZ * D_ENC / 128, 128>>>(ctx_out);
}